// round 6
// baseline (speedup 1.0000x reference)
#include <cuda_runtime.h>
#include <cuda_bf16.h>

// MeanAggregator: out[i] = mean over edges e with segment_ids[e]==i of
// features[neighbor_idx[e]], zero row if no edges. segment_ids is SORTED.
//
// Inputs (metadata order) — NOTE: JAX x64 disabled => int64 degrades to int32:
//   d_in[0] features     float32 [N=50000, D=128]
//   d_in[1] neighbor_idx int32   [E=1600000]
//   d_in[2] segment_ids  int32   [E=1600000]  (sorted ascending)
// Output: float32 [N, D]

#define MAX_NODES 50001

__device__ int g_row_start[MAX_NODES + 1];  // row_start[i] = first edge of segment i

// --- Kernel 1: segment boundaries from sorted segment_ids -------------------
// row_start[s] = e  where seg[e-1] < s <= seg[e]  (sentinels seg[-1]=-1, seg[E]=N)
__global__ void boundary_kernel(const int* __restrict__ seg, int E, int N) {
    int e = blockIdx.x * blockDim.x + threadIdx.x;
    if (e > E) return;
    int prev = (e == 0) ? -1 : seg[e - 1];
    int cur  = (e == E) ? N : seg[e];
    if (cur > N) cur = N;           // defensive clamp
    for (int s = prev + 1; s <= cur; s++) {
        g_row_start[s] = e;
    }
}

// --- Kernel 2: one warp per node, float4 per lane (512B row per warp) -------
__global__ void __launch_bounds__(256, 8) mean_agg_kernel(
    const float4* __restrict__ features,      // [N, 32] float4
    const int* __restrict__ neighbor,         // [E]
    float4* __restrict__ out,                 // [N, 32] float4
    int N)
{
    int warp_in_blk = threadIdx.x >> 5;
    int lane        = threadIdx.x & 31;
    int node        = blockIdx.x * 8 + warp_in_blk;
    if (node >= N) return;

    int s = g_row_start[node];
    int e = g_row_start[node + 1];
    int cnt = e - s;

    float ax = 0.f, ay = 0.f, az = 0.f, aw = 0.f;

    for (int base = s; base < e; base += 32) {
        int n = e - base;
        if (n > 32) n = 32;
        // coalesced load of up to 32 edge indices, one per lane
        int myidx = (lane < n) ? __ldg(&neighbor[base + lane]) : 0;
        int j = 0;
        // unrolled-by-4 broadcast loop: 4 independent 512B row loads in flight
        for (; j + 4 <= n; j += 4) {
            int i0 = __shfl_sync(0xffffffffu, myidx, j + 0);
            int i1 = __shfl_sync(0xffffffffu, myidx, j + 1);
            int i2 = __shfl_sync(0xffffffffu, myidx, j + 2);
            int i3 = __shfl_sync(0xffffffffu, myidx, j + 3);
            float4 f0 = __ldg(&features[(long long)i0 * 32 + lane]);
            float4 f1 = __ldg(&features[(long long)i1 * 32 + lane]);
            float4 f2 = __ldg(&features[(long long)i2 * 32 + lane]);
            float4 f3 = __ldg(&features[(long long)i3 * 32 + lane]);
            ax += f0.x; ay += f0.y; az += f0.z; aw += f0.w;
            ax += f1.x; ay += f1.y; az += f1.z; aw += f1.w;
            ax += f2.x; ay += f2.y; az += f2.z; aw += f2.w;
            ax += f3.x; ay += f3.y; az += f3.z; aw += f3.w;
        }
        for (; j < n; j++) {
            int i0 = __shfl_sync(0xffffffffu, myidx, j);
            float4 f0 = __ldg(&features[(long long)i0 * 32 + lane]);
            ax += f0.x; ay += f0.y; az += f0.z; aw += f0.w;
        }
    }

    float inv = (cnt > 0) ? (1.0f / (float)cnt) : 0.0f;
    float4 r;
    r.x = ax * inv; r.y = ay * inv; r.z = az * inv; r.w = aw * inv;
    out[(long long)node * 32 + lane] = r;
}

extern "C" void kernel_launch(void* const* d_in, const int* in_sizes, int n_in,
                              void* d_out, int out_size) {
    const float* features = (const float*)d_in[0];
    const int*   neighbor = (const int*)d_in[1];
    const int*   seg      = (const int*)d_in[2];
    float*       out      = (float*)d_out;

    int E = in_sizes[1];            // 1600000
    int N = out_size / 128;         // 50000
    if (N > MAX_NODES) N = MAX_NODES;

    // Kernel 1: segment boundaries
    {
        int threads = 256;
        int blocks  = (E + 1 + threads - 1) / threads;
        boundary_kernel<<<blocks, threads>>>(seg, E, N);
    }
    // Kernel 2: aggregation, one warp per node
    {
        int threads = 256;                 // 8 warps = 8 nodes per block
        int blocks  = (N + 7) / 8;
        mean_agg_kernel<<<blocks, threads>>>(
            (const float4*)features, neighbor, (float4*)out, N);
    }
}